// round 15
// baseline (speedup 1.0000x reference)
#include <cuda_runtime.h>
#include <math.h>

#define SPLIT 32
#define CHP 132          // per-warp key capacity (CH = ceil(4097/32) = 129)
#define KSQ 16           // k-splits for QKV proj (slice 256)
#define KSO 16           // k-splits for out proj (slice 256)

// ---------------- scratch (no allocations allowed) ----------------
// x / attn-out in mma A-fragment order: [octet(k/8)][lane][4 slots], hi & lo tf32 parts
__device__ float g_xfh[512 * 128];
__device__ float g_xfl[512 * 128];
__device__ float g_afh[512 * 128];
__device__ float g_afl[512 * 128];
__device__ float g_qkv[6144 * 16];                     // k(4096..5119)/v(5120..6143) rows x 16 batches
__device__ float g_qT[16 * 4096];                      // q contiguous per (b, head): [b][qh*128+d]
__device__ float g_partQ[KSQ * 6144 * 16];             // QKV proj k-split partials
__device__ float g_partO[KSO * 4096 * 16];             // out proj k-split partials
__device__ float g_part_o[16 * 8 * 4 * SPLIT * 128];   // split-KV partial outputs
__device__ float g_part_ml[16 * 8 * 4 * SPLIT * 2];    // split-KV partial (m, l)

// ---------------- helpers ----------------
__device__ __forceinline__ float ex2f_fast(float x) {
    float y;
    asm("ex2.approx.ftz.f32 %0, %1;" : "=f"(y) : "f"(x));
    return y;
}
__device__ __forceinline__ unsigned tf32_rna(float v) {
    unsigned u;
    asm("cvt.rna.tf32.f32 %0, %1;" : "=r"(u) : "f"(v));
    return u;
}
// fragment index for value at (k, b): A[m=b][k] of the m16n8k8 tile
__device__ __forceinline__ int frag_idx(int k, int b) {
    int oct = k >> 3;
    int lane = ((b & 7) << 2) | (k & 3);
    int slot = (((k >> 2) & 1) << 1) | (b >> 3);
    return oct * 128 + lane * 4 + slot;
}

#define MMA_TF32(c, a, b0_, b1_)                                              \
    asm volatile("mma.sync.aligned.m16n8k8.row.col.f32.tf32.tf32.f32 "        \
        "{%0,%1,%2,%3}, {%4,%5,%6,%7}, {%8,%9}, {%0,%1,%2,%3};"               \
        : "+f"((c)[0]), "+f"((c)[1]), "+f"((c)[2]), "+f"((c)[3])              \
        : "r"((a)[0]), "r"((a)[1]), "r"((a)[2]), "r"((a)[3]),                 \
          "r"(b0_), "r"(b1_))

// 4-value warp sum reduction, 5 SHFL. Lane l ends holding full sum of value (l&3).
__device__ __forceinline__ float red4x(float s0, float s1, float s2, float s3, int lane) {
    const bool b1 = lane & 2;
    float t0 = b1 ? s2 : s0;
    float t1 = b1 ? s3 : s1;
    float u0 = b1 ? s0 : s2;
    float u1 = b1 ? s1 : s3;
    t0 += __shfl_xor_sync(0xffffffffu, u0, 2);
    t1 += __shfl_xor_sync(0xffffffffu, u1, 2);
    const bool b0 = lane & 1;
    float r = b0 ? t1 : t0;
    float w = b0 ? t0 : t1;
    r += __shfl_xor_sync(0xffffffffu, w, 1);
    r += __shfl_xor_sync(0xffffffffu, r, 4);
    r += __shfl_xor_sync(0xffffffffu, r, 8);
    r += __shfl_xor_sync(0xffffffffu, r, 16);
    return r;
}
// 4-value warp max reduction, 5 SHFL.
__device__ __forceinline__ float red4m(float s0, float s1, float s2, float s3, int lane) {
    const bool b1 = lane & 2;
    float t0 = b1 ? s2 : s0;
    float t1 = b1 ? s3 : s1;
    float u0 = b1 ? s0 : s2;
    float u1 = b1 ? s1 : s3;
    t0 = fmaxf(t0, __shfl_xor_sync(0xffffffffu, u0, 2));
    t1 = fmaxf(t1, __shfl_xor_sync(0xffffffffu, u1, 2));
    const bool b0 = lane & 1;
    float r = b0 ? t1 : t0;
    float w = b0 ? t0 : t1;
    r = fmaxf(r, __shfl_xor_sync(0xffffffffu, w, 1));
    r = fmaxf(r, __shfl_xor_sync(0xffffffffu, r, 4));
    r = fmaxf(r, __shfl_xor_sync(0xffffffffu, r, 8));
    r = fmaxf(r, __shfl_xor_sync(0xffffffffu, r, 16));
    return r;
}

// ---------------- kernel 0: dummy (x2 launches put ncu capture slot on gemv_mma QKV) ----------------
__global__ void dummy_kernel() {}

// ---------------- kernel 1: prep x — transpose + tf32 hi/lo split into fragment layout ----------------
__global__ void prep_x_kernel(const float* __restrict__ x) {
    __shared__ float t[16][17];
    const int k0 = blockIdx.x * 16;
    t[threadIdx.y][threadIdx.x] = x[threadIdx.y * 4096 + k0 + threadIdx.x];
    __syncthreads();
    float v = t[threadIdx.x][threadIdx.y];
    const int k = k0 + threadIdx.y, b = threadIdx.x;
    float hif = __uint_as_float(tf32_rna(v));
    float lof = v - hif;
    int fi = frag_idx(k, b);
    g_xfh[fi] = hif;
    g_xfl[fi] = __uint_as_float(tf32_rna(lof));
}

// ---------------- kernel 2/7: TF32 3x mma projection ----------------
// C[m=batch16][n=rows] = x^T * W^T over a k-slice (256); partials to gmem.
// Block: 128 thr = 4 warps; warp = 16 rows (2 n8-tiles). 64 rows/block.
// Low-reg tile => ~10 blocks/SM => single wave at 1536 blocks.
__global__ __launch_bounds__(128, 8) void gemv_mma_kernel(
    const float* __restrict__ Wa, const float* __restrict__ Wb, const float* __restrict__ Wc,
    int mode)
{
    const int lane = threadIdx.x & 31, wid = threadIdx.x >> 5;
    const int qr = lane >> 2, qc = lane & 3;

    const int rowBlock = blockIdx.x >> 4;
    const int ks = blockIdx.x & 15;
    const int kslice = 256;
    const float* xfh;
    const float* xfl;
    float* part;
    int nrows;
    if (mode == 0) { xfh = g_xfh; xfl = g_xfl; part = g_partQ; nrows = 6144; }
    else           { xfh = g_afh; xfl = g_afl; part = g_partO; nrows = 4096; }

    const int rowBase = rowBlock * 64 + wid * 16;
    const int k0 = ks * kslice;

    const float* W = Wa;
    int wrow = rowBase;
    if (mode == 0) {
        if (rowBase >= 5120)      { W = Wc; wrow = rowBase - 5120; }
        else if (rowBase >= 4096) { W = Wb; wrow = rowBase - 4096; }
    }

    float cm0[4] = {0,0,0,0}, cm1[4] = {0,0,0,0};
    float cx0[4] = {0,0,0,0}, cx1[4] = {0,0,0,0};

    const float* wbase = W + (size_t)(wrow + qr) * 4096 + qc;

    for (int kk = k0; kk < k0 + kslice; kk += 16) {
        // ---- front-batch all loads for 2 octets (8 weight LDG.32 + 4 x LDG.128) ----
        float w0[2][2], w1[2][2];   // [oct][tile]
#pragma unroll
        for (int o = 0; o < 2; o++)
#pragma unroll
            for (int t = 0; t < 2; t++) {
                const float* wp = wbase + (size_t)t * 8 * 4096 + kk + o * 8;
                w0[o][t] = wp[0];
                w1[o][t] = wp[4];
            }
        float4 ahf[2], alf[2];
#pragma unroll
        for (int o = 0; o < 2; o++) {
            ahf[o] = *(const float4*)(xfh + (((kk >> 3) + o) * 128 + lane * 4));
            alf[o] = *(const float4*)(xfl + (((kk >> 3) + o) * 128 + lane * 4));
        }
        // ---- per octet: converts + 3 mma per tile ----
#pragma unroll
        for (int o = 0; o < 2; o++) {
            unsigned ah[4] = {__float_as_uint(ahf[o].x), __float_as_uint(ahf[o].y),
                              __float_as_uint(ahf[o].z), __float_as_uint(ahf[o].w)};
            unsigned al[4] = {__float_as_uint(alf[o].x), __float_as_uint(alf[o].y),
                              __float_as_uint(alf[o].z), __float_as_uint(alf[o].w)};
#define DO_TILE(T, CM, CX)                                                    \
            {                                                                 \
                unsigned bh0 = tf32_rna(w0[o][T]), bh1 = tf32_rna(w1[o][T]);  \
                float l0 = w0[o][T] - __uint_as_float(bh0);                   \
                float l1 = w1[o][T] - __uint_as_float(bh1);                   \
                unsigned bl0 = tf32_rna(l0), bl1 = tf32_rna(l1);              \
                MMA_TF32(CM, ah, bh0, bh1);                                   \
                MMA_TF32(CX, ah, bl0, bl1);                                   \
                MMA_TF32(CX, al, bh0, bh1);                                   \
            }
            DO_TILE(0, cm0, cx0)
            DO_TILE(1, cm1, cx1)
#undef DO_TILE
        }
    }

#define STORE_TILE(T, CM, CX)                                                 \
    {                                                                         \
        int r = rowBase + (T) * 8 + qc * 2;                                   \
        size_t base = ((size_t)ks * nrows + r) * 16;                          \
        part[base + qr]           = CM[0] + CX[0];                            \
        part[base + 16 + qr]      = CM[1] + CX[1];                            \
        part[base + qr + 8]       = CM[2] + CX[2];                            \
        part[base + 16 + qr + 8]  = CM[3] + CX[3];                            \
    }
    STORE_TILE(0, cm0, cx0)
    STORE_TILE(1, cm1, cx1)
#undef STORE_TILE
}

// ---------------- kernel 3: QKV combine — sum k-splits + RoPE + scale ----------------
__global__ void qkv_combine_kernel(const float* __restrict__ fc, const float* __restrict__ fs) {
    const int idx = blockIdx.x * 256 + threadIdx.x;   // 49152 = 3072 rowpairs x 16 b
    const int rp = idx >> 4, b = idx & 15;
    const int r = rp * 2;
    float v0 = 0.f, v1 = 0.f;
#pragma unroll 8
    for (int ks = 0; ks < KSQ; ks++) {
        v0 += g_partQ[((size_t)ks * 6144 + r) * 16 + b];
        v1 += g_partQ[((size_t)ks * 6144 + r + 1) * 16 + b];
    }
    if (r < 5120) {   // RoPE for q and k rows
        int i0 = (r & 127) >> 1;
        float c0 = fc[i0], s0 = fs[i0];
        float a0 = v0 * c0 - v1 * s0, b0 = v0 * s0 + v1 * c0;
        v0 = a0; v1 = b0;
        if (r < 4096) {   // fold softmax scale * log2(e) into q
            const float SC = 1.4426950408889634f * 0.08838834764831843f;
            v0 *= SC; v1 *= SC;
        }
    }
    if (r < 4096) {
        g_qT[b * 4096 + r] = v0;
        g_qT[b * 4096 + r + 1] = v1;
    } else {
        g_qkv[r * 16 + b] = v0;
        g_qkv[(r + 1) * 16 + b] = v1;
    }
}

// ---------------- kernel 4: split-KV flash-decode partials (warp = kv-head) ----------------
__global__ __launch_bounds__(256, 4) void attn_partial_kernel(
    const float* __restrict__ cache_k, const float* __restrict__ cache_v,
    const int* __restrict__ sp_ptr)
{
    __shared__ __align__(16) float sc[8][CHP * 4];

    const int tid = threadIdx.x, lane = tid & 31, wid = tid >> 5;
    const int blk = blockIdx.x;
    const int chunk = blk % SPLIT;
    const int b = blk / SPLIT;
    const int kvh = wid;
    const int sp = *sp_ptr;
    const int kvlen = sp + 1;
    const int CH = (kvlen + SPLIT - 1) / SPLIT;
    const int c0 = chunk * CH;
    const int c1 = min(c0 + CH, kvlen);
    const int len = c1 - c0;
    const bool has_new = (sp >= c0 && sp < c1);
    const int jmax = min(c1, sp);
    float* scw = sc[wid];

    if (len <= 0) return;

    float4 qv[4];
#pragma unroll
    for (int h = 0; h < 4; h++)
        qv[h] = *(const float4*)(g_qT + b * 4096 + (kvh * 4 + h) * 128 + lane * 4);

    const float* kbase = cache_k + (size_t)b * 8192 * 1024 + kvh * 128 + lane * 4;
    const float* vbase = cache_v + (size_t)b * 8192 * 1024 + kvh * 128 + lane * 4;

#define DOT4(kk, d0, d1, d2, d3)                                             \
    do {                                                                     \
        d0 = kk.x*qv[0].x + kk.y*qv[0].y + kk.z*qv[0].z + kk.w*qv[0].w;      \
        d1 = kk.x*qv[1].x + kk.y*qv[1].y + kk.z*qv[1].z + kk.w*qv[1].w;      \
        d2 = kk.x*qv[2].x + kk.y*qv[2].y + kk.z*qv[2].z + kk.w*qv[2].w;      \
        d3 = kk.x*qv[3].x + kk.y*qv[3].y + kk.z*qv[3].z + kk.w*qv[3].w;      \
    } while (0)

    // ---- Phase A: scores ----
    {
        int j = c0;
        for (; j + 3 < jmax; j += 4) {
            float4 k0 = *(const float4*)(kbase + (size_t)(j + 0) * 1024);
            float4 k1 = *(const float4*)(kbase + (size_t)(j + 1) * 1024);
            float4 k2 = *(const float4*)(kbase + (size_t)(j + 2) * 1024);
            float4 k3 = *(const float4*)(kbase + (size_t)(j + 3) * 1024);
            float a0,a1,a2,a3, b0,b1,b2,b3, c0s,c1s,c2s,c3s, d0,d1,d2,d3;
            DOT4(k0, a0,a1,a2,a3);
            DOT4(k1, b0,b1,b2,b3);
            DOT4(k2, c0s,c1s,c2s,c3s);
            DOT4(k3, d0,d1,d2,d3);
            float ra = red4x(a0,a1,a2,a3, lane);
            float rb = red4x(b0,b1,b2,b3, lane);
            float rc = red4x(c0s,c1s,c2s,c3s, lane);
            float rd = red4x(d0,d1,d2,d3, lane);
            if (lane < 4) {
                int jj = (j - c0) * 4 + lane;
                scw[jj] = ra; scw[jj + 4] = rb; scw[jj + 8] = rc; scw[jj + 12] = rd;
            }
        }
        for (; j < jmax; j++) {
            float4 k0 = *(const float4*)(kbase + (size_t)j * 1024);
            float a0,a1,a2,a3;
            DOT4(k0, a0,a1,a2,a3);
            float ra = red4x(a0,a1,a2,a3, lane);
            if (lane < 4) scw[(j - c0) * 4 + lane] = ra;
        }
        if (has_new) {
            int base = (4096 + kvh * 128 + lane * 4) * 16 + b;
            float4 kv;
            kv.x = g_qkv[base]; kv.y = g_qkv[base + 16]; kv.z = g_qkv[base + 32]; kv.w = g_qkv[base + 48];
            float a0,a1,a2,a3;
            DOT4(kv, a0,a1,a2,a3);
            float ra = red4x(a0,a1,a2,a3, lane);
            if (lane < 4) scw[(sp - c0) * 4 + lane] = ra;
        }
    }
    __syncwarp();

    // ---- warp-private max per head ----
    float4 mx = make_float4(-1e30f, -1e30f, -1e30f, -1e30f);
    const float4* scw4 = (const float4*)scw;
    for (int i = lane; i < len; i += 32) {
        float4 t = scw4[i];
        mx.x = fmaxf(mx.x, t.x); mx.y = fmaxf(mx.y, t.y);
        mx.z = fmaxf(mx.z, t.z); mx.w = fmaxf(mx.w, t.w);
    }
    float rm = red4m(mx.x, mx.y, mx.z, mx.w, lane);
    const float m0 = __shfl_sync(0xffffffffu, rm, 0);
    const float m1 = __shfl_sync(0xffffffffu, rm, 1);
    const float m2 = __shfl_sync(0xffffffffu, rm, 2);
    const float m3 = __shfl_sync(0xffffffffu, rm, 3);

    // ---- exp2 pass + row sums ----
    float4 ls = make_float4(0.f, 0.f, 0.f, 0.f);
    float4* scw4w = (float4*)scw;
    for (int i = lane; i < len; i += 32) {
        float4 t = scw4w[i];
        t.x = ex2f_fast(t.x - m0); t.y = ex2f_fast(t.y - m1);
        t.z = ex2f_fast(t.z - m2); t.w = ex2f_fast(t.w - m3);
        scw4w[i] = t;
        ls.x += t.x; ls.y += t.y; ls.z += t.z; ls.w += t.w;
    }
    float rl = red4x(ls.x, ls.y, ls.z, ls.w, lane);
    __syncwarp();

    // ---- Phase B: weighted V accumulation ----
    float4 o0 = {0,0,0,0}, o1 = {0,0,0,0}, o2 = {0,0,0,0}, o3 = {0,0,0,0};
    {
        int j = c0;
        for (; j + 3 < jmax; j += 4) {
            float4 v0 = *(const float4*)(vbase + (size_t)(j + 0) * 1024);
            float4 v1 = *(const float4*)(vbase + (size_t)(j + 1) * 1024);
            float4 v2 = *(const float4*)(vbase + (size_t)(j + 2) * 1024);
            float4 v3 = *(const float4*)(vbase + (size_t)(j + 3) * 1024);
            float4 p0 = scw4[(j - c0) + 0];
            float4 p1 = scw4[(j - c0) + 1];
            float4 p2 = scw4[(j - c0) + 2];
            float4 p3 = scw4[(j - c0) + 3];
            o0.x += p0.x*v0.x + p1.x*v1.x + p2.x*v2.x + p3.x*v3.x;
            o0.y += p0.x*v0.y + p1.x*v1.y + p2.x*v2.y + p3.x*v3.y;
            o0.z += p0.x*v0.z + p1.x*v1.z + p2.x*v2.z + p3.x*v3.z;
            o0.w += p0.x*v0.w + p1.x*v1.w + p2.x*v2.w + p3.x*v3.w;
            o1.x += p0.y*v0.x + p1.y*v1.x + p2.y*v2.x + p3.y*v3.x;
            o1.y += p0.y*v0.y + p1.y*v1.y + p2.y*v2.y + p3.y*v3.y;
            o1.z += p0.y*v0.z + p1.y*v1.z + p2.y*v2.z + p3.y*v3.z;
            o1.w += p0.y*v0.w + p1.y*v1.w + p2.y*v2.w + p3.y*v3.w;
            o2.x += p0.z*v0.x + p1.z*v1.x + p2.z*v2.x + p3.z*v3.x;
            o2.y += p0.z*v0.y + p1.z*v1.y + p2.z*v2.y + p3.z*v3.y;
            o2.z += p0.z*v0.z + p1.z*v1.z + p2.z*v2.z + p3.z*v3.z;
            o2.w += p0.z*v0.w + p1.z*v1.w + p2.z*v2.w + p3.z*v3.w;
            o3.x += p0.w*v0.x + p1.w*v1.x + p2.w*v2.x + p3.w*v3.x;
            o3.y += p0.w*v0.y + p1.w*v1.y + p2.w*v2.y + p3.w*v3.y;
            o3.z += p0.w*v0.z + p1.w*v1.z + p2.w*v2.z + p3.w*v3.z;
            o3.w += p0.w*v0.w + p1.w*v1.w + p2.w*v2.w + p3.w*v3.w;
        }
        for (; j < jmax; j++) {
            float4 v0 = *(const float4*)(vbase + (size_t)j * 1024);
            float4 p0 = scw4[j - c0];
            o0.x += p0.x*v0.x; o0.y += p0.x*v0.y; o0.z += p0.x*v0.z; o0.w += p0.x*v0.w;
            o1.x += p0.y*v0.x; o1.y += p0.y*v0.y; o1.z += p0.y*v0.z; o1.w += p0.y*v0.w;
            o2.x += p0.z*v0.x; o2.y += p0.z*v0.y; o2.z += p0.z*v0.z; o2.w += p0.z*v0.w;
            o3.x += p0.w*v0.x; o3.y += p0.w*v0.y; o3.z += p0.w*v0.z; o3.w += p0.w*v0.w;
        }
        if (has_new) {
            int base = (5120 + kvh * 128 + lane * 4) * 16 + b;
            float4 vv;
            vv.x = g_qkv[base]; vv.y = g_qkv[base + 16]; vv.z = g_qkv[base + 32]; vv.w = g_qkv[base + 48];
            float4 p0 = scw4[sp - c0];
            o0.x += p0.x*vv.x; o0.y += p0.x*vv.y; o0.z += p0.x*vv.z; o0.w += p0.x*vv.w;
            o1.x += p0.y*vv.x; o1.y += p0.y*vv.y; o1.z += p0.y*vv.z; o1.w += p0.y*vv.w;
            o2.x += p0.z*vv.x; o2.y += p0.z*vv.y; o2.z += p0.z*vv.z; o2.w += p0.z*vv.w;
            o3.x += p0.w*vv.x; o3.y += p0.w*vv.y; o3.z += p0.w*vv.z; o3.w += p0.w*vv.w;
        }
    }

    // ---- per-warp partial writes ----
    {
        const int hb = ((b * 8 + kvh) * 4) * SPLIT + chunk;
        *(float4*)(g_part_o + (size_t)(hb + 0 * SPLIT) * 128 + lane * 4) = o0;
        *(float4*)(g_part_o + (size_t)(hb + 1 * SPLIT) * 128 + lane * 4) = o1;
        *(float4*)(g_part_o + (size_t)(hb + 2 * SPLIT) * 128 + lane * 4) = o2;
        *(float4*)(g_part_o + (size_t)(hb + 3 * SPLIT) * 128 + lane * 4) = o3;
        if (lane < 4) {
            int pidx = hb + lane * SPLIT;
            g_part_ml[pidx * 2]     = rm;
            g_part_ml[pidx * 2 + 1] = rl;
        }
    }
}

// ---------------- kernel 5: split-KV softmax combine -> attn out fragments (tf32 hi/lo) ----------------
__global__ void attn_combine_kernel() {
    const int qh = blockIdx.x & 31;
    const int b = blockIdx.x >> 5;
    const int kvh = qh >> 2, h = qh & 3;
    const int pidx = ((b * 8 + kvh) * 4 + h) * SPLIT;
    const int d = threadIdx.x;

    float M = -1e30f;
#pragma unroll
    for (int g = 0; g < SPLIT; g++)
        M = fmaxf(M, g_part_ml[(pidx + g) * 2]);

    float L = 0.f, s = 0.f;
#pragma unroll 4
    for (int g = 0; g < SPLIT; g++) {
        float w = ex2f_fast(g_part_ml[(pidx + g) * 2] - M);
        L += g_part_ml[(pidx + g) * 2 + 1] * w;
        s += g_part_o[(size_t)(pidx + g) * 128 + d] * w;
    }

    float v = s / L;
    float hif = __uint_as_float(tf32_rna(v));
    float lof = v - hif;
    int fi = frag_idx(qh * 128 + d, b);
    g_afh[fi] = hif;
    g_afl[fi] = __uint_as_float(tf32_rna(lof));
}

// ---------------- kernel 8: out combine — sum k-splits -> final output ----------------
__global__ void out_combine_kernel(float* __restrict__ outp) {
    const int idx = blockIdx.x * 256 + threadIdx.x;   // 65536 = 16 b x 4096 rows
    const int b = idx >> 12, r = idx & 4095;
    float s = 0.f;
#pragma unroll 8
    for (int ks = 0; ks < KSO; ks++)
        s += g_partO[((size_t)ks * 4096 + r) * 16 + b];
    outp[b * 4096 + r] = s;
}

// ---------------- launch ----------------
extern "C" void kernel_launch(void* const* d_in, const int* in_sizes, int n_in,
                              void* d_out, int out_size) {
    const float* x  = (const float*)d_in[0];
    const int*   sp = (const int*)d_in[1];
    const float* fc = (const float*)d_in[2];
    const float* fs = (const float*)d_in[3];
    const float* ck = (const float*)d_in[4];
    const float* cv = (const float*)d_in[5];
    const float* wq = (const float*)d_in[6];
    const float* wk = (const float*)d_in[7];
    const float* wv = (const float*)d_in[8];
    const float* wo = (const float*)d_in[9];
    float* out = (float*)d_out;

    dummy_kernel<<<1, 32>>>();
    dummy_kernel<<<1, 32>>>();
    prep_x_kernel<<<256, dim3(16, 16)>>>(x);
    gemv_mma_kernel<<<96 * KSQ, 128>>>(wq, wk, wv, 0);           // QKV projection (1536 blocks)
    qkv_combine_kernel<<<192, 256>>>(fc, fs);
    attn_partial_kernel<<<16 * SPLIT, 256>>>(ck, cv, sp);
    attn_combine_kernel<<<512, 128>>>();
    gemv_mma_kernel<<<64 * KSO, 128>>>(wo, nullptr, nullptr, 1); // out projection (1024 blocks)
    out_combine_kernel<<<256, 256>>>(out);
}

// round 16
// speedup vs baseline: 1.3086x; 1.3086x over previous
#include <cuda_runtime.h>
#include <math.h>

#define SPLIT 32
#define CHP 132          // per-warp key capacity (CH = ceil(4097/32) = 129)
#define KSQ 16           // k-splits for QKV proj (slice 256)
#define KSO 32           // k-splits for out proj (slice 128)

// ---------------- scratch (no allocations allowed) ----------------
// x / attn-out in mma A-fragment order: [octet(k/8)][lane][4 slots], hi & lo tf32 parts
__device__ float g_xfh[512 * 128];
__device__ float g_xfl[512 * 128];
__device__ float g_afh[512 * 128];
__device__ float g_afl[512 * 128];
__device__ float g_qkv[6144 * 16];                     // k(4096..5119)/v(5120..6143) rows x 16 batches
__device__ float g_qT[16 * 4096];                      // q contiguous per (b, head): [b][qh*128+d]
__device__ float g_partQ[KSQ * 6144 * 16];             // QKV proj k-split partials
__device__ float g_partO[KSO * 4096 * 16];             // out proj k-split partials
__device__ float g_part_o[16 * 8 * 4 * SPLIT * 128];   // split-KV partial outputs
__device__ float g_part_ml[16 * 8 * 4 * SPLIT * 2];    // split-KV partial (m, l)

// ---------------- helpers ----------------
__device__ __forceinline__ float ex2f_fast(float x) {
    float y;
    asm("ex2.approx.ftz.f32 %0, %1;" : "=f"(y) : "f"(x));
    return y;
}
__device__ __forceinline__ unsigned tf32_rna(float v) {
    unsigned u;
    asm("cvt.rna.tf32.f32 %0, %1;" : "=r"(u) : "f"(v));
    return u;
}
// fragment index for value at (k, b): A[m=b][k] of the m16n8k8 tile
__device__ __forceinline__ int frag_idx(int k, int b) {
    int oct = k >> 3;
    int lane = ((b & 7) << 2) | (k & 3);
    int slot = (((k >> 2) & 1) << 1) | (b >> 3);
    return oct * 128 + lane * 4 + slot;
}

#define MMA_TF32(c, a, b0_, b1_)                                              \
    asm volatile("mma.sync.aligned.m16n8k8.row.col.f32.tf32.tf32.f32 "        \
        "{%0,%1,%2,%3}, {%4,%5,%6,%7}, {%8,%9}, {%0,%1,%2,%3};"               \
        : "+f"((c)[0]), "+f"((c)[1]), "+f"((c)[2]), "+f"((c)[3])              \
        : "r"((a)[0]), "r"((a)[1]), "r"((a)[2]), "r"((a)[3]),                 \
          "r"(b0_), "r"(b1_))

// 4-value warp sum reduction, 5 SHFL. Lane l ends holding full sum of value (l&3).
__device__ __forceinline__ float red4x(float s0, float s1, float s2, float s3, int lane) {
    const bool b1 = lane & 2;
    float t0 = b1 ? s2 : s0;
    float t1 = b1 ? s3 : s1;
    float u0 = b1 ? s0 : s2;
    float u1 = b1 ? s1 : s3;
    t0 += __shfl_xor_sync(0xffffffffu, u0, 2);
    t1 += __shfl_xor_sync(0xffffffffu, u1, 2);
    const bool b0 = lane & 1;
    float r = b0 ? t1 : t0;
    float w = b0 ? t0 : t1;
    r += __shfl_xor_sync(0xffffffffu, w, 1);
    r += __shfl_xor_sync(0xffffffffu, r, 4);
    r += __shfl_xor_sync(0xffffffffu, r, 8);
    r += __shfl_xor_sync(0xffffffffu, r, 16);
    return r;
}
// 4-value warp max reduction, 5 SHFL.
__device__ __forceinline__ float red4m(float s0, float s1, float s2, float s3, int lane) {
    const bool b1 = lane & 2;
    float t0 = b1 ? s2 : s0;
    float t1 = b1 ? s3 : s1;
    float u0 = b1 ? s0 : s2;
    float u1 = b1 ? s1 : s3;
    t0 = fmaxf(t0, __shfl_xor_sync(0xffffffffu, u0, 2));
    t1 = fmaxf(t1, __shfl_xor_sync(0xffffffffu, u1, 2));
    const bool b0 = lane & 1;
    float r = b0 ? t1 : t0;
    float w = b0 ? t0 : t1;
    r = fmaxf(r, __shfl_xor_sync(0xffffffffu, w, 1));
    r = fmaxf(r, __shfl_xor_sync(0xffffffffu, r, 4));
    r = fmaxf(r, __shfl_xor_sync(0xffffffffu, r, 8));
    r = fmaxf(r, __shfl_xor_sync(0xffffffffu, r, 16));
    return r;
}

// ---------------- kernel 0: dummy (x2 launches put ncu capture slot on gemv_mma QKV) ----------------
__global__ void dummy_kernel() {}

// ---------------- kernel 1: prep x — transpose + tf32 hi/lo split into fragment layout ----------------
__global__ void prep_x_kernel(const float* __restrict__ x) {
    __shared__ float t[16][17];
    const int k0 = blockIdx.x * 16;
    t[threadIdx.y][threadIdx.x] = x[threadIdx.y * 4096 + k0 + threadIdx.x];
    __syncthreads();
    float v = t[threadIdx.x][threadIdx.y];
    const int k = k0 + threadIdx.y, b = threadIdx.x;
    float hif = __uint_as_float(tf32_rna(v));
    float lof = v - hif;
    int fi = frag_idx(k, b);
    g_xfh[fi] = hif;
    g_xfl[fi] = __uint_as_float(tf32_rna(lof));
}

// ---------------- kernel 2/7: TF32 3x mma projection ----------------
// C[m=batch16][n=rows] = x^T * W^T over a k-slice; partials to gmem.
// Block: 128 thr = 4 warps; warp = 32 rows (4 n8-tiles). 128 rows/block.
// mode 0: QKV, KSQ=16 splits (kslice 256), grid 48*16=768 — single wave
// mode 1: out, KSO=32 splits (kslice 128), grid 32*32=1024 — single wave
__global__ __launch_bounds__(128, 8) void gemv_mma_kernel(
    const float* __restrict__ Wa, const float* __restrict__ Wb, const float* __restrict__ Wc,
    int mode)
{
    const int lane = threadIdx.x & 31, wid = threadIdx.x >> 5;
    const int qr = lane >> 2, qc = lane & 3;

    int rowBlock, ks, kslice;
    const float* xfh;
    const float* xfl;
    float* part;
    int nrows;
    if (mode == 0) {
        rowBlock = blockIdx.x >> 4; ks = blockIdx.x & 15; kslice = 256;
        xfh = g_xfh; xfl = g_xfl; part = g_partQ; nrows = 6144;
    } else {
        rowBlock = blockIdx.x >> 5; ks = blockIdx.x & 31; kslice = 128;
        xfh = g_afh; xfl = g_afl; part = g_partO; nrows = 4096;
    }

    const int rowBase = rowBlock * 128 + wid * 32;
    const int k0 = ks * kslice;

    const float* W = Wa;
    int wrow = rowBase;
    if (mode == 0) {
        if (rowBase >= 5120)      { W = Wc; wrow = rowBase - 5120; }
        else if (rowBase >= 4096) { W = Wb; wrow = rowBase - 4096; }
    }

    float cm0[4] = {0,0,0,0}, cm1[4] = {0,0,0,0}, cm2[4] = {0,0,0,0}, cm3[4] = {0,0,0,0};
    float cx0[4] = {0,0,0,0}, cx1[4] = {0,0,0,0}, cx2[4] = {0,0,0,0}, cx3[4] = {0,0,0,0};

    const float* wbase = W + (size_t)(wrow + qr) * 4096 + qc;

#pragma unroll 4
    for (int kk = k0; kk < k0 + kslice; kk += 8) {
        // front-batch weight loads (DRAM)
        float w0[4], w1[4];
#pragma unroll
        for (int t = 0; t < 4; t++) {
            const float* wp = wbase + (size_t)t * 8 * 4096 + kk;
            w0[t] = wp[0];
            w1[t] = wp[4];
        }
        // A fragments: one LDG.128 each for hi / lo
        float4 ahf = *(const float4*)(xfh + ((kk >> 3) * 128 + lane * 4));
        float4 alf = *(const float4*)(xfl + ((kk >> 3) * 128 + lane * 4));
        unsigned ah[4] = {__float_as_uint(ahf.x), __float_as_uint(ahf.y),
                          __float_as_uint(ahf.z), __float_as_uint(ahf.w)};
        unsigned al[4] = {__float_as_uint(alf.x), __float_as_uint(alf.y),
                          __float_as_uint(alf.z), __float_as_uint(alf.w)};
#define DO_TILE(T, CM, CX)                                                    \
        {                                                                     \
            unsigned bh0 = tf32_rna(w0[T]), bh1 = tf32_rna(w1[T]);            \
            float l0 = w0[T] - __uint_as_float(bh0);                          \
            float l1 = w1[T] - __uint_as_float(bh1);                          \
            unsigned bl0 = tf32_rna(l0), bl1 = tf32_rna(l1);                  \
            MMA_TF32(CM, ah, bh0, bh1);                                       \
            MMA_TF32(CX, ah, bl0, bl1);                                       \
            MMA_TF32(CX, al, bh0, bh1);                                       \
        }
        DO_TILE(0, cm0, cx0)
        DO_TILE(1, cm1, cx1)
        DO_TILE(2, cm2, cx2)
        DO_TILE(3, cm3, cx3)
#undef DO_TILE
    }

#define STORE_TILE(T, CM, CX)                                                 \
    {                                                                         \
        int r = rowBase + (T) * 8 + qc * 2;                                   \
        size_t base = ((size_t)ks * nrows + r) * 16;                          \
        part[base + qr]           = CM[0] + CX[0];                            \
        part[base + 16 + qr]      = CM[1] + CX[1];                            \
        part[base + qr + 8]       = CM[2] + CX[2];                            \
        part[base + 16 + qr + 8]  = CM[3] + CX[3];                            \
    }
    STORE_TILE(0, cm0, cx0)
    STORE_TILE(1, cm1, cx1)
    STORE_TILE(2, cm2, cx2)
    STORE_TILE(3, cm3, cx3)
#undef STORE_TILE
}

// ---------------- kernel 3: QKV combine — sum k-splits + RoPE + scale ----------------
__global__ void qkv_combine_kernel(const float* __restrict__ fc, const float* __restrict__ fs) {
    const int idx = blockIdx.x * 256 + threadIdx.x;   // 49152 = 3072 rowpairs x 16 b
    const int rp = idx >> 4, b = idx & 15;
    const int r = rp * 2;
    float v0 = 0.f, v1 = 0.f;
#pragma unroll 8
    for (int ks = 0; ks < KSQ; ks++) {
        v0 += g_partQ[((size_t)ks * 6144 + r) * 16 + b];
        v1 += g_partQ[((size_t)ks * 6144 + r + 1) * 16 + b];
    }
    if (r < 5120) {   // RoPE for q and k rows
        int i0 = (r & 127) >> 1;
        float c0 = fc[i0], s0 = fs[i0];
        float a0 = v0 * c0 - v1 * s0, b0 = v0 * s0 + v1 * c0;
        v0 = a0; v1 = b0;
        if (r < 4096) {   // fold softmax scale * log2(e) into q
            const float SC = 1.4426950408889634f * 0.08838834764831843f;
            v0 *= SC; v1 *= SC;
        }
    }
    if (r < 4096) {
        g_qT[b * 4096 + r] = v0;
        g_qT[b * 4096 + r + 1] = v1;
    } else {
        g_qkv[r * 16 + b] = v0;
        g_qkv[(r + 1) * 16 + b] = v1;
    }
}

// ---------------- kernel 4: split-KV flash-decode partials (warp = kv-head) ----------------
__global__ __launch_bounds__(256, 4) void attn_partial_kernel(
    const float* __restrict__ cache_k, const float* __restrict__ cache_v,
    const int* __restrict__ sp_ptr)
{
    __shared__ __align__(16) float sc[8][CHP * 4];

    const int tid = threadIdx.x, lane = tid & 31, wid = tid >> 5;
    const int blk = blockIdx.x;
    const int chunk = blk % SPLIT;
    const int b = blk / SPLIT;
    const int kvh = wid;
    const int sp = *sp_ptr;
    const int kvlen = sp + 1;
    const int CH = (kvlen + SPLIT - 1) / SPLIT;
    const int c0 = chunk * CH;
    const int c1 = min(c0 + CH, kvlen);
    const int len = c1 - c0;
    const bool has_new = (sp >= c0 && sp < c1);
    const int jmax = min(c1, sp);
    float* scw = sc[wid];

    if (len <= 0) return;

    float4 qv[4];
#pragma unroll
    for (int h = 0; h < 4; h++)
        qv[h] = *(const float4*)(g_qT + b * 4096 + (kvh * 4 + h) * 128 + lane * 4);

    const float* kbase = cache_k + (size_t)b * 8192 * 1024 + kvh * 128 + lane * 4;
    const float* vbase = cache_v + (size_t)b * 8192 * 1024 + kvh * 128 + lane * 4;

#define DOT4(kk, d0, d1, d2, d3)                                             \
    do {                                                                     \
        d0 = kk.x*qv[0].x + kk.y*qv[0].y + kk.z*qv[0].z + kk.w*qv[0].w;      \
        d1 = kk.x*qv[1].x + kk.y*qv[1].y + kk.z*qv[1].z + kk.w*qv[1].w;      \
        d2 = kk.x*qv[2].x + kk.y*qv[2].y + kk.z*qv[2].z + kk.w*qv[2].w;      \
        d3 = kk.x*qv[3].x + kk.y*qv[3].y + kk.z*qv[3].z + kk.w*qv[3].w;      \
    } while (0)

    // ---- Phase A: scores ----
    {
        int j = c0;
        for (; j + 3 < jmax; j += 4) {
            float4 k0 = *(const float4*)(kbase + (size_t)(j + 0) * 1024);
            float4 k1 = *(const float4*)(kbase + (size_t)(j + 1) * 1024);
            float4 k2 = *(const float4*)(kbase + (size_t)(j + 2) * 1024);
            float4 k3 = *(const float4*)(kbase + (size_t)(j + 3) * 1024);
            float a0,a1,a2,a3, b0,b1,b2,b3, c0s,c1s,c2s,c3s, d0,d1,d2,d3;
            DOT4(k0, a0,a1,a2,a3);
            DOT4(k1, b0,b1,b2,b3);
            DOT4(k2, c0s,c1s,c2s,c3s);
            DOT4(k3, d0,d1,d2,d3);
            float ra = red4x(a0,a1,a2,a3, lane);
            float rb = red4x(b0,b1,b2,b3, lane);
            float rc = red4x(c0s,c1s,c2s,c3s, lane);
            float rd = red4x(d0,d1,d2,d3, lane);
            if (lane < 4) {
                int jj = (j - c0) * 4 + lane;
                scw[jj] = ra; scw[jj + 4] = rb; scw[jj + 8] = rc; scw[jj + 12] = rd;
            }
        }
        for (; j < jmax; j++) {
            float4 k0 = *(const float4*)(kbase + (size_t)j * 1024);
            float a0,a1,a2,a3;
            DOT4(k0, a0,a1,a2,a3);
            float ra = red4x(a0,a1,a2,a3, lane);
            if (lane < 4) scw[(j - c0) * 4 + lane] = ra;
        }
        if (has_new) {
            int base = (4096 + kvh * 128 + lane * 4) * 16 + b;
            float4 kv;
            kv.x = g_qkv[base]; kv.y = g_qkv[base + 16]; kv.z = g_qkv[base + 32]; kv.w = g_qkv[base + 48];
            float a0,a1,a2,a3;
            DOT4(kv, a0,a1,a2,a3);
            float ra = red4x(a0,a1,a2,a3, lane);
            if (lane < 4) scw[(sp - c0) * 4 + lane] = ra;
        }
    }
    __syncwarp();

    // ---- warp-private max per head ----
    float4 mx = make_float4(-1e30f, -1e30f, -1e30f, -1e30f);
    const float4* scw4 = (const float4*)scw;
    for (int i = lane; i < len; i += 32) {
        float4 t = scw4[i];
        mx.x = fmaxf(mx.x, t.x); mx.y = fmaxf(mx.y, t.y);
        mx.z = fmaxf(mx.z, t.z); mx.w = fmaxf(mx.w, t.w);
    }
    float rm = red4m(mx.x, mx.y, mx.z, mx.w, lane);
    const float m0 = __shfl_sync(0xffffffffu, rm, 0);
    const float m1 = __shfl_sync(0xffffffffu, rm, 1);
    const float m2 = __shfl_sync(0xffffffffu, rm, 2);
    const float m3 = __shfl_sync(0xffffffffu, rm, 3);

    // ---- exp2 pass + row sums ----
    float4 ls = make_float4(0.f, 0.f, 0.f, 0.f);
    float4* scw4w = (float4*)scw;
    for (int i = lane; i < len; i += 32) {
        float4 t = scw4w[i];
        t.x = ex2f_fast(t.x - m0); t.y = ex2f_fast(t.y - m1);
        t.z = ex2f_fast(t.z - m2); t.w = ex2f_fast(t.w - m3);
        scw4w[i] = t;
        ls.x += t.x; ls.y += t.y; ls.z += t.z; ls.w += t.w;
    }
    float rl = red4x(ls.x, ls.y, ls.z, ls.w, lane);
    __syncwarp();

    // ---- Phase B: weighted V accumulation ----
    float4 o0 = {0,0,0,0}, o1 = {0,0,0,0}, o2 = {0,0,0,0}, o3 = {0,0,0,0};
    {
        int j = c0;
        for (; j + 3 < jmax; j += 4) {
            float4 v0 = *(const float4*)(vbase + (size_t)(j + 0) * 1024);
            float4 v1 = *(const float4*)(vbase + (size_t)(j + 1) * 1024);
            float4 v2 = *(const float4*)(vbase + (size_t)(j + 2) * 1024);
            float4 v3 = *(const float4*)(vbase + (size_t)(j + 3) * 1024);
            float4 p0 = scw4[(j - c0) + 0];
            float4 p1 = scw4[(j - c0) + 1];
            float4 p2 = scw4[(j - c0) + 2];
            float4 p3 = scw4[(j - c0) + 3];
            o0.x += p0.x*v0.x + p1.x*v1.x + p2.x*v2.x + p3.x*v3.x;
            o0.y += p0.x*v0.y + p1.x*v1.y + p2.x*v2.y + p3.x*v3.y;
            o0.z += p0.x*v0.z + p1.x*v1.z + p2.x*v2.z + p3.x*v3.z;
            o0.w += p0.x*v0.w + p1.x*v1.w + p2.x*v2.w + p3.x*v3.w;
            o1.x += p0.y*v0.x + p1.y*v1.x + p2.y*v2.x + p3.y*v3.x;
            o1.y += p0.y*v0.y + p1.y*v1.y + p2.y*v2.y + p3.y*v3.y;
            o1.z += p0.y*v0.z + p1.y*v1.z + p2.y*v2.z + p3.y*v3.z;
            o1.w += p0.y*v0.w + p1.y*v1.w + p2.y*v2.w + p3.y*v3.w;
            o2.x += p0.z*v0.x + p1.z*v1.x + p2.z*v2.x + p3.z*v3.x;
            o2.y += p0.z*v0.y + p1.z*v1.y + p2.z*v2.y + p3.z*v3.y;
            o2.z += p0.z*v0.z + p1.z*v1.z + p2.z*v2.z + p3.z*v3.z;
            o2.w += p0.z*v0.w + p1.z*v1.w + p2.z*v2.w + p3.z*v3.w;
            o3.x += p0.w*v0.x + p1.w*v1.x + p2.w*v2.x + p3.w*v3.x;
            o3.y += p0.w*v0.y + p1.w*v1.y + p2.w*v2.y + p3.w*v3.y;
            o3.z += p0.w*v0.z + p1.w*v1.z + p2.w*v2.z + p3.w*v3.z;
            o3.w += p0.w*v0.w + p1.w*v1.w + p2.w*v2.w + p3.w*v3.w;
        }
        for (; j < jmax; j++) {
            float4 v0 = *(const float4*)(vbase + (size_t)j * 1024);
            float4 p0 = scw4[j - c0];
            o0.x += p0.x*v0.x; o0.y += p0.x*v0.y; o0.z += p0.x*v0.z; o0.w += p0.x*v0.w;
            o1.x += p0.y*v0.x; o1.y += p0.y*v0.y; o1.z += p0.y*v0.z; o1.w += p0.y*v0.w;
            o2.x += p0.z*v0.x; o2.y += p0.z*v0.y; o2.z += p0.z*v0.z; o2.w += p0.z*v0.w;
            o3.x += p0.w*v0.x; o3.y += p0.w*v0.y; o3.z += p0.w*v0.z; o3.w += p0.w*v0.w;
        }
        if (has_new) {
            int base = (5120 + kvh * 128 + lane * 4) * 16 + b;
            float4 vv;
            vv.x = g_qkv[base]; vv.y = g_qkv[base + 16]; vv.z = g_qkv[base + 32]; vv.w = g_qkv[base + 48];
            float4 p0 = scw4[sp - c0];
            o0.x += p0.x*vv.x; o0.y += p0.x*vv.y; o0.z += p0.x*vv.z; o0.w += p0.x*vv.w;
            o1.x += p0.y*vv.x; o1.y += p0.y*vv.y; o1.z += p0.y*vv.z; o1.w += p0.y*vv.w;
            o2.x += p0.z*vv.x; o2.y += p0.z*vv.y; o2.z += p0.z*vv.z; o2.w += p0.z*vv.w;
            o3.x += p0.w*vv.x; o3.y += p0.w*vv.y; o3.z += p0.w*vv.z; o3.w += p0.w*vv.w;
        }
    }

    // ---- per-warp partial writes ----
    {
        const int hb = ((b * 8 + kvh) * 4) * SPLIT + chunk;
        *(float4*)(g_part_o + (size_t)(hb + 0 * SPLIT) * 128 + lane * 4) = o0;
        *(float4*)(g_part_o + (size_t)(hb + 1 * SPLIT) * 128 + lane * 4) = o1;
        *(float4*)(g_part_o + (size_t)(hb + 2 * SPLIT) * 128 + lane * 4) = o2;
        *(float4*)(g_part_o + (size_t)(hb + 3 * SPLIT) * 128 + lane * 4) = o3;
        if (lane < 4) {
            int pidx = hb + lane * SPLIT;
            g_part_ml[pidx * 2]     = rm;
            g_part_ml[pidx * 2 + 1] = rl;
        }
    }
}

// ---------------- kernel 5: split-KV softmax combine -> attn out fragments (tf32 hi/lo) ----------------
__global__ void attn_combine_kernel() {
    const int qh = blockIdx.x & 31;
    const int b = blockIdx.x >> 5;
    const int kvh = qh >> 2, h = qh & 3;
    const int pidx = ((b * 8 + kvh) * 4 + h) * SPLIT;
    const int d = threadIdx.x;

    float M = -1e30f;
#pragma unroll
    for (int g = 0; g < SPLIT; g++)
        M = fmaxf(M, g_part_ml[(pidx + g) * 2]);

    float L = 0.f, s = 0.f;
#pragma unroll 4
    for (int g = 0; g < SPLIT; g++) {
        float w = ex2f_fast(g_part_ml[(pidx + g) * 2] - M);
        L += g_part_ml[(pidx + g) * 2 + 1] * w;
        s += g_part_o[(size_t)(pidx + g) * 128 + d] * w;
    }

    float v = s / L;
    float hif = __uint_as_float(tf32_rna(v));
    float lof = v - hif;
    int fi = frag_idx(qh * 128 + d, b);
    g_afh[fi] = hif;
    g_afl[fi] = __uint_as_float(tf32_rna(lof));
}

// ---------------- kernel 8: out combine — sum k-splits -> final output ----------------
__global__ void out_combine_kernel(float* __restrict__ outp) {
    const int idx = blockIdx.x * 256 + threadIdx.x;   // 65536 = 16 b x 4096 rows
    const int b = idx >> 12, r = idx & 4095;
    float s = 0.f;
#pragma unroll 8
    for (int ks = 0; ks < KSO; ks++)
        s += g_partO[((size_t)ks * 4096 + r) * 16 + b];
    outp[b * 4096 + r] = s;
}

// ---------------- launch ----------------
extern "C" void kernel_launch(void* const* d_in, const int* in_sizes, int n_in,
                              void* d_out, int out_size) {
    const float* x  = (const float*)d_in[0];
    const int*   sp = (const int*)d_in[1];
    const float* fc = (const float*)d_in[2];
    const float* fs = (const float*)d_in[3];
    const float* ck = (const float*)d_in[4];
    const float* cv = (const float*)d_in[5];
    const float* wq = (const float*)d_in[6];
    const float* wk = (const float*)d_in[7];
    const float* wv = (const float*)d_in[8];
    const float* wo = (const float*)d_in[9];
    float* out = (float*)d_out;

    dummy_kernel<<<1, 32>>>();
    dummy_kernel<<<1, 32>>>();
    prep_x_kernel<<<256, dim3(16, 16)>>>(x);
    gemv_mma_kernel<<<48 * KSQ, 128>>>(wq, wk, wv, 0);           // QKV projection (768 blocks)
    qkv_combine_kernel<<<192, 256>>>(fc, fs);
    attn_partial_kernel<<<16 * SPLIT, 256>>>(ck, cv, sp);
    attn_combine_kernel<<<512, 128>>>();
    gemv_mma_kernel<<<32 * KSO, 128>>>(wo, nullptr, nullptr, 1); // out projection (1024 blocks)
    out_combine_kernel<<<256, 256>>>(out);
}

// round 17
// speedup vs baseline: 1.3947x; 1.0658x over previous
#include <cuda_runtime.h>
#include <math.h>

#define SPLIT 32
#define CHP 132          // per-warp key capacity (CH = ceil(4097/32) = 129)
#define KSQ 16           // k-splits for QKV proj (slice 256)
#define KSO 16           // k-splits for out proj (slice 256)

// ---------------- scratch (no allocations allowed) ----------------
// x / attn-out in mma A-fragment order: [octet(k/8)][lane][4 slots], hi & lo tf32 parts
__device__ float g_xfh[512 * 128];
__device__ float g_xfl[512 * 128];
__device__ float g_afh[512 * 128];
__device__ float g_afl[512 * 128];
__device__ float g_qkv[6144 * 16];                     // k(4096..5119)/v(5120..6143) rows x 16 batches
__device__ float g_qT[16 * 4096];                      // q contiguous per (b, head): [b][qh*128+d]
__device__ float g_partQ[KSQ * 6144 * 16];             // QKV proj k-split partials
__device__ float g_partO[KSO * 4096 * 16];             // out proj k-split partials
__device__ float g_part_o[16 * 8 * 4 * SPLIT * 128];   // split-KV partial outputs
__device__ float g_part_ml[16 * 8 * 4 * SPLIT * 2];    // split-KV partial (m, l)

// ---------------- helpers ----------------
__device__ __forceinline__ float ex2f_fast(float x) {
    float y;
    asm("ex2.approx.ftz.f32 %0, %1;" : "=f"(y) : "f"(x));
    return y;
}
__device__ __forceinline__ unsigned tf32_rna(float v) {
    unsigned u;
    asm("cvt.rna.tf32.f32 %0, %1;" : "=r"(u) : "f"(v));
    return u;
}
__device__ __forceinline__ unsigned smem_u32(const void* p) {
    unsigned a;
    asm("{ .reg .u64 t; cvta.to.shared.u64 t, %1; cvt.u32.u64 %0, t; }" : "=r"(a) : "l"(p));
    return a;
}
__device__ __forceinline__ void cp_async16(unsigned dst, const void* src) {
    asm volatile("cp.async.cg.shared.global [%0], [%1], 16;" :: "r"(dst), "l"(src));
}
__device__ __forceinline__ void cp_commit() { asm volatile("cp.async.commit_group;"); }
__device__ __forceinline__ void cp_wait0() { asm volatile("cp.async.wait_group 0;"); }

// fragment index for value at (k, b): A[m=b][k] of the m16n8k8 tile
__device__ __forceinline__ int frag_idx(int k, int b) {
    int oct = k >> 3;
    int lane = ((b & 7) << 2) | (k & 3);
    int slot = (((k >> 2) & 1) << 1) | (b >> 3);
    return oct * 128 + lane * 4 + slot;
}

#define MMA_TF32(c, a, b0_, b1_)                                              \
    asm volatile("mma.sync.aligned.m16n8k8.row.col.f32.tf32.tf32.f32 "        \
        "{%0,%1,%2,%3}, {%4,%5,%6,%7}, {%8,%9}, {%0,%1,%2,%3};"               \
        : "+f"((c)[0]), "+f"((c)[1]), "+f"((c)[2]), "+f"((c)[3])              \
        : "r"((a)[0]), "r"((a)[1]), "r"((a)[2]), "r"((a)[3]),                 \
          "r"(b0_), "r"(b1_))

// 4-value warp sum reduction, 5 SHFL. Lane l ends holding full sum of value (l&3).
__device__ __forceinline__ float red4x(float s0, float s1, float s2, float s3, int lane) {
    const bool b1 = lane & 2;
    float t0 = b1 ? s2 : s0;
    float t1 = b1 ? s3 : s1;
    float u0 = b1 ? s0 : s2;
    float u1 = b1 ? s1 : s3;
    t0 += __shfl_xor_sync(0xffffffffu, u0, 2);
    t1 += __shfl_xor_sync(0xffffffffu, u1, 2);
    const bool b0 = lane & 1;
    float r = b0 ? t1 : t0;
    float w = b0 ? t0 : t1;
    r += __shfl_xor_sync(0xffffffffu, w, 1);
    r += __shfl_xor_sync(0xffffffffu, r, 4);
    r += __shfl_xor_sync(0xffffffffu, r, 8);
    r += __shfl_xor_sync(0xffffffffu, r, 16);
    return r;
}
// 4-value warp max reduction, 5 SHFL.
__device__ __forceinline__ float red4m(float s0, float s1, float s2, float s3, int lane) {
    const bool b1 = lane & 2;
    float t0 = b1 ? s2 : s0;
    float t1 = b1 ? s3 : s1;
    float u0 = b1 ? s0 : s2;
    float u1 = b1 ? s1 : s3;
    t0 = fmaxf(t0, __shfl_xor_sync(0xffffffffu, u0, 2));
    t1 = fmaxf(t1, __shfl_xor_sync(0xffffffffu, u1, 2));
    const bool b0 = lane & 1;
    float r = b0 ? t1 : t0;
    float w = b0 ? t0 : t1;
    r = fmaxf(r, __shfl_xor_sync(0xffffffffu, w, 1));
    r = fmaxf(r, __shfl_xor_sync(0xffffffffu, r, 4));
    r = fmaxf(r, __shfl_xor_sync(0xffffffffu, r, 8));
    r = fmaxf(r, __shfl_xor_sync(0xffffffffu, r, 16));
    return r;
}

// ---------------- kernel 0: dummy (x2 launches put ncu capture slot on gemv_mma QKV) ----------------
__global__ void dummy_kernel() {}

// ---------------- kernel 1: prep x — transpose + tf32 hi/lo split into fragment layout ----------------
__global__ void prep_x_kernel(const float* __restrict__ x) {
    __shared__ float t[16][17];
    const int k0 = blockIdx.x * 16;
    t[threadIdx.y][threadIdx.x] = x[threadIdx.y * 4096 + k0 + threadIdx.x];
    __syncthreads();
    float v = t[threadIdx.x][threadIdx.y];
    const int k = k0 + threadIdx.y, b = threadIdx.x;
    float hif = __uint_as_float(tf32_rna(v));
    float lof = v - hif;
    int fi = frag_idx(k, b);
    g_xfh[fi] = hif;
    g_xfl[fi] = __uint_as_float(tf32_rna(lof));
}

// ---------------- kernel 2/7: TF32 3x mma projection with smem-staged weights ----------------
// C[m=batch16][n=rows] = x^T * W^T over a 256-k slice; partials to gmem.
// Block: 128 thr = 4 warps; warp = 32 rows (4 n8-tiles); 128 rows/block.
// Weight tile staged per 64-k chunk via cp.async (coalesced), consumed via
// conflict-free LDS (row pitch 68 -> banks qr*4+qc).
__global__ __launch_bounds__(128, 6) void gemv_mma_kernel(
    const float* __restrict__ Wa, const float* __restrict__ Wb, const float* __restrict__ Wc,
    int mode)
{
    __shared__ __align__(16) float ws[128][68];   // 34.8 KB

    const int tid = threadIdx.x;
    const int lane = tid & 31, wid = tid >> 5;
    const int qr = lane >> 2, qc = lane & 3;

    const int rowBlock = blockIdx.x >> 4;
    const int ks = blockIdx.x & 15;
    const int kslice = 256;
    const float* xfh;
    const float* xfl;
    float* part;
    int nrows;
    if (mode == 0) { xfh = g_xfh; xfl = g_xfl; part = g_partQ; nrows = 6144; }
    else           { xfh = g_afh; xfl = g_afl; part = g_partO; nrows = 4096; }

    const int rowBase = rowBlock * 128 + wid * 32;
    const int k0 = ks * kslice;

    const float* W = Wa;
    int wrow = rowBase;
    if (mode == 0) {
        if (rowBase >= 5120)      { W = Wc; wrow = rowBase - 5120; }
        else if (rowBase >= 4096) { W = Wb; wrow = rowBase - 4096; }
    }
    const int wrowBlk = wrow - wid * 32;   // block's first W row

    float cm0[4] = {0,0,0,0}, cm1[4] = {0,0,0,0}, cm2[4] = {0,0,0,0}, cm3[4] = {0,0,0,0};
    float cx0[4] = {0,0,0,0}, cx1[4] = {0,0,0,0}, cx2[4] = {0,0,0,0}, cx3[4] = {0,0,0,0};

    const unsigned ws_base = smem_u32(&ws[0][0]);
    const int lrow = wid * 32 + qr;   // this lane's tile-0 row in ws

    for (int c = 0; c < 4; c++) {
        const int kc = k0 + c * 64;
        // ---- stage 128x64 W tile (coalesced cp.async, 16 B each) ----
        {
            const float* wsrc = W + (size_t)wrowBlk * 4096 + kc;
#pragma unroll
            for (int u = 0; u < 16; u++) {
                int fidx = tid + u * 128;
                int r = fidx >> 4, j4 = fidx & 15;
                cp_async16(ws_base + ((unsigned)(r * 68 + j4 * 4) << 2),
                           wsrc + (size_t)r * 4096 + j4 * 4);
            }
            cp_commit();
            cp_wait0();
            __syncthreads();
        }
        // ---- compute 8 octets from smem ----
#pragma unroll
        for (int o = 0; o < 8; o++) {
            const int kk = kc + o * 8;
            const int kl = o * 8;
            float4 ahf = *(const float4*)(xfh + ((kk >> 3) * 128 + lane * 4));
            float4 alf = *(const float4*)(xfl + ((kk >> 3) * 128 + lane * 4));
            unsigned ah[4] = {__float_as_uint(ahf.x), __float_as_uint(ahf.y),
                              __float_as_uint(ahf.z), __float_as_uint(ahf.w)};
            unsigned al[4] = {__float_as_uint(alf.x), __float_as_uint(alf.y),
                              __float_as_uint(alf.z), __float_as_uint(alf.w)};
#define DO_TILE(T, CM, CX)                                                    \
            {                                                                 \
                const float* wp = &ws[lrow + (T) * 8][kl + qc];               \
                float w0 = wp[0], w1 = wp[4];                                 \
                unsigned bh0 = tf32_rna(w0), bh1 = tf32_rna(w1);              \
                float l0 = w0 - __uint_as_float(bh0);                         \
                float l1 = w1 - __uint_as_float(bh1);                         \
                unsigned bl0 = tf32_rna(l0), bl1 = tf32_rna(l1);              \
                MMA_TF32(CM, ah, bh0, bh1);                                   \
                MMA_TF32(CX, ah, bl0, bl1);                                   \
                MMA_TF32(CX, al, bh0, bh1);                                   \
            }
            DO_TILE(0, cm0, cx0)
            DO_TILE(1, cm1, cx1)
            DO_TILE(2, cm2, cx2)
            DO_TILE(3, cm3, cx3)
#undef DO_TILE
        }
        __syncthreads();
    }

#define STORE_TILE(T, CM, CX)                                                 \
    {                                                                         \
        int r = rowBase + (T) * 8 + qc * 2;                                   \
        size_t base = ((size_t)ks * nrows + r) * 16;                          \
        part[base + qr]           = CM[0] + CX[0];                            \
        part[base + 16 + qr]      = CM[1] + CX[1];                            \
        part[base + qr + 8]       = CM[2] + CX[2];                            \
        part[base + 16 + qr + 8]  = CM[3] + CX[3];                            \
    }
    STORE_TILE(0, cm0, cx0)
    STORE_TILE(1, cm1, cx1)
    STORE_TILE(2, cm2, cx2)
    STORE_TILE(3, cm3, cx3)
#undef STORE_TILE
}

// ---------------- kernel 3: QKV combine — sum k-splits + RoPE + scale ----------------
__global__ void qkv_combine_kernel(const float* __restrict__ fc, const float* __restrict__ fs) {
    const int idx = blockIdx.x * 256 + threadIdx.x;   // 49152 = 3072 rowpairs x 16 b
    const int rp = idx >> 4, b = idx & 15;
    const int r = rp * 2;
    float v0 = 0.f, v1 = 0.f;
#pragma unroll 8
    for (int ks = 0; ks < KSQ; ks++) {
        v0 += g_partQ[((size_t)ks * 6144 + r) * 16 + b];
        v1 += g_partQ[((size_t)ks * 6144 + r + 1) * 16 + b];
    }
    if (r < 5120) {   // RoPE for q and k rows
        int i0 = (r & 127) >> 1;
        float c0 = fc[i0], s0 = fs[i0];
        float a0 = v0 * c0 - v1 * s0, b0 = v0 * s0 + v1 * c0;
        v0 = a0; v1 = b0;
        if (r < 4096) {   // fold softmax scale * log2(e) into q
            const float SC = 1.4426950408889634f * 0.08838834764831843f;
            v0 *= SC; v1 *= SC;
        }
    }
    if (r < 4096) {
        g_qT[b * 4096 + r] = v0;
        g_qT[b * 4096 + r + 1] = v1;
    } else {
        g_qkv[r * 16 + b] = v0;
        g_qkv[(r + 1) * 16 + b] = v1;
    }
}

// ---------------- kernel 4: split-KV flash-decode partials (warp = kv-head) ----------------
__global__ __launch_bounds__(256, 4) void attn_partial_kernel(
    const float* __restrict__ cache_k, const float* __restrict__ cache_v,
    const int* __restrict__ sp_ptr)
{
    __shared__ __align__(16) float sc[8][CHP * 4];

    const int tid = threadIdx.x, lane = tid & 31, wid = tid >> 5;
    const int blk = blockIdx.x;
    const int chunk = blk % SPLIT;
    const int b = blk / SPLIT;
    const int kvh = wid;
    const int sp = *sp_ptr;
    const int kvlen = sp + 1;
    const int CH = (kvlen + SPLIT - 1) / SPLIT;
    const int c0 = chunk * CH;
    const int c1 = min(c0 + CH, kvlen);
    const int len = c1 - c0;
    const bool has_new = (sp >= c0 && sp < c1);
    const int jmax = min(c1, sp);
    float* scw = sc[wid];

    if (len <= 0) return;

    float4 qv[4];
#pragma unroll
    for (int h = 0; h < 4; h++)
        qv[h] = *(const float4*)(g_qT + b * 4096 + (kvh * 4 + h) * 128 + lane * 4);

    const float* kbase = cache_k + (size_t)b * 8192 * 1024 + kvh * 128 + lane * 4;
    const float* vbase = cache_v + (size_t)b * 8192 * 1024 + kvh * 128 + lane * 4;

#define DOT4(kk, d0, d1, d2, d3)                                             \
    do {                                                                     \
        d0 = kk.x*qv[0].x + kk.y*qv[0].y + kk.z*qv[0].z + kk.w*qv[0].w;      \
        d1 = kk.x*qv[1].x + kk.y*qv[1].y + kk.z*qv[1].z + kk.w*qv[1].w;      \
        d2 = kk.x*qv[2].x + kk.y*qv[2].y + kk.z*qv[2].z + kk.w*qv[2].w;      \
        d3 = kk.x*qv[3].x + kk.y*qv[3].y + kk.z*qv[3].z + kk.w*qv[3].w;      \
    } while (0)

    // ---- Phase A: scores ----
    {
        int j = c0;
        for (; j + 3 < jmax; j += 4) {
            float4 k0 = *(const float4*)(kbase + (size_t)(j + 0) * 1024);
            float4 k1 = *(const float4*)(kbase + (size_t)(j + 1) * 1024);
            float4 k2 = *(const float4*)(kbase + (size_t)(j + 2) * 1024);
            float4 k3 = *(const float4*)(kbase + (size_t)(j + 3) * 1024);
            float a0,a1,a2,a3, b0,b1,b2,b3, c0s,c1s,c2s,c3s, d0,d1,d2,d3;
            DOT4(k0, a0,a1,a2,a3);
            DOT4(k1, b0,b1,b2,b3);
            DOT4(k2, c0s,c1s,c2s,c3s);
            DOT4(k3, d0,d1,d2,d3);
            float ra = red4x(a0,a1,a2,a3, lane);
            float rb = red4x(b0,b1,b2,b3, lane);
            float rc = red4x(c0s,c1s,c2s,c3s, lane);
            float rd = red4x(d0,d1,d2,d3, lane);
            if (lane < 4) {
                int jj = (j - c0) * 4 + lane;
                scw[jj] = ra; scw[jj + 4] = rb; scw[jj + 8] = rc; scw[jj + 12] = rd;
            }
        }
        for (; j < jmax; j++) {
            float4 k0 = *(const float4*)(kbase + (size_t)j * 1024);
            float a0,a1,a2,a3;
            DOT4(k0, a0,a1,a2,a3);
            float ra = red4x(a0,a1,a2,a3, lane);
            if (lane < 4) scw[(j - c0) * 4 + lane] = ra;
        }
        if (has_new) {
            int base = (4096 + kvh * 128 + lane * 4) * 16 + b;
            float4 kv;
            kv.x = g_qkv[base]; kv.y = g_qkv[base + 16]; kv.z = g_qkv[base + 32]; kv.w = g_qkv[base + 48];
            float a0,a1,a2,a3;
            DOT4(kv, a0,a1,a2,a3);
            float ra = red4x(a0,a1,a2,a3, lane);
            if (lane < 4) scw[(sp - c0) * 4 + lane] = ra;
        }
    }
    __syncwarp();

    // ---- warp-private max per head ----
    float4 mx = make_float4(-1e30f, -1e30f, -1e30f, -1e30f);
    const float4* scw4 = (const float4*)scw;
    for (int i = lane; i < len; i += 32) {
        float4 t = scw4[i];
        mx.x = fmaxf(mx.x, t.x); mx.y = fmaxf(mx.y, t.y);
        mx.z = fmaxf(mx.z, t.z); mx.w = fmaxf(mx.w, t.w);
    }
    float rm = red4m(mx.x, mx.y, mx.z, mx.w, lane);
    const float m0 = __shfl_sync(0xffffffffu, rm, 0);
    const float m1 = __shfl_sync(0xffffffffu, rm, 1);
    const float m2 = __shfl_sync(0xffffffffu, rm, 2);
    const float m3 = __shfl_sync(0xffffffffu, rm, 3);

    // ---- exp2 pass + row sums ----
    float4 ls = make_float4(0.f, 0.f, 0.f, 0.f);
    float4* scw4w = (float4*)scw;
    for (int i = lane; i < len; i += 32) {
        float4 t = scw4w[i];
        t.x = ex2f_fast(t.x - m0); t.y = ex2f_fast(t.y - m1);
        t.z = ex2f_fast(t.z - m2); t.w = ex2f_fast(t.w - m3);
        scw4w[i] = t;
        ls.x += t.x; ls.y += t.y; ls.z += t.z; ls.w += t.w;
    }
    float rl = red4x(ls.x, ls.y, ls.z, ls.w, lane);
    __syncwarp();

    // ---- Phase B: weighted V accumulation ----
    float4 o0 = {0,0,0,0}, o1 = {0,0,0,0}, o2 = {0,0,0,0}, o3 = {0,0,0,0};
    {
        int j = c0;
        for (; j + 3 < jmax; j += 4) {
            float4 v0 = *(const float4*)(vbase + (size_t)(j + 0) * 1024);
            float4 v1 = *(const float4*)(vbase + (size_t)(j + 1) * 1024);
            float4 v2 = *(const float4*)(vbase + (size_t)(j + 2) * 1024);
            float4 v3 = *(const float4*)(vbase + (size_t)(j + 3) * 1024);
            float4 p0 = scw4[(j - c0) + 0];
            float4 p1 = scw4[(j - c0) + 1];
            float4 p2 = scw4[(j - c0) + 2];
            float4 p3 = scw4[(j - c0) + 3];
            o0.x += p0.x*v0.x + p1.x*v1.x + p2.x*v2.x + p3.x*v3.x;
            o0.y += p0.x*v0.y + p1.x*v1.y + p2.x*v2.y + p3.x*v3.y;
            o0.z += p0.x*v0.z + p1.x*v1.z + p2.x*v2.z + p3.x*v3.z;
            o0.w += p0.x*v0.w + p1.x*v1.w + p2.x*v2.w + p3.x*v3.w;
            o1.x += p0.y*v0.x + p1.y*v1.x + p2.y*v2.x + p3.y*v3.x;
            o1.y += p0.y*v0.y + p1.y*v1.y + p2.y*v2.y + p3.y*v3.y;
            o1.z += p0.y*v0.z + p1.y*v1.z + p2.y*v2.z + p3.y*v3.z;
            o1.w += p0.y*v0.w + p1.y*v1.w + p2.y*v2.w + p3.y*v3.w;
            o2.x += p0.z*v0.x + p1.z*v1.x + p2.z*v2.x + p3.z*v3.x;
            o2.y += p0.z*v0.y + p1.z*v1.y + p2.z*v2.y + p3.z*v3.y;
            o2.z += p0.z*v0.z + p1.z*v1.z + p2.z*v2.z + p3.z*v3.z;
            o2.w += p0.z*v0.w + p1.z*v1.w + p2.z*v2.w + p3.z*v3.w;
            o3.x += p0.w*v0.x + p1.w*v1.x + p2.w*v2.x + p3.w*v3.x;
            o3.y += p0.w*v0.y + p1.w*v1.y + p2.w*v2.y + p3.w*v3.y;
            o3.z += p0.w*v0.z + p1.w*v1.z + p2.w*v2.z + p3.w*v3.z;
            o3.w += p0.w*v0.w + p1.w*v1.w + p2.w*v2.w + p3.w*v3.w;
        }
        for (; j < jmax; j++) {
            float4 v0 = *(const float4*)(vbase + (size_t)j * 1024);
            float4 p0 = scw4[j - c0];
            o0.x += p0.x*v0.x; o0.y += p0.x*v0.y; o0.z += p0.x*v0.z; o0.w += p0.x*v0.w;
            o1.x += p0.y*v0.x; o1.y += p0.y*v0.y; o1.z += p0.y*v0.z; o1.w += p0.y*v0.w;
            o2.x += p0.z*v0.x; o2.y += p0.z*v0.y; o2.z += p0.z*v0.z; o2.w += p0.z*v0.w;
            o3.x += p0.w*v0.x; o3.y += p0.w*v0.y; o3.z += p0.w*v0.z; o3.w += p0.w*v0.w;
        }
        if (has_new) {
            int base = (5120 + kvh * 128 + lane * 4) * 16 + b;
            float4 vv;
            vv.x = g_qkv[base]; vv.y = g_qkv[base + 16]; vv.z = g_qkv[base + 32]; vv.w = g_qkv[base + 48];
            float4 p0 = scw4[sp - c0];
            o0.x += p0.x*vv.x; o0.y += p0.x*vv.y; o0.z += p0.x*vv.z; o0.w += p0.x*vv.w;
            o1.x += p0.y*vv.x; o1.y += p0.y*vv.y; o1.z += p0.y*vv.z; o1.w += p0.y*vv.w;
            o2.x += p0.z*vv.x; o2.y += p0.z*vv.y; o2.z += p0.z*vv.z; o2.w += p0.z*vv.w;
            o3.x += p0.w*vv.x; o3.y += p0.w*vv.y; o3.z += p0.w*vv.z; o3.w += p0.w*vv.w;
        }
    }

    // ---- per-warp partial writes ----
    {
        const int hb = ((b * 8 + kvh) * 4) * SPLIT + chunk;
        *(float4*)(g_part_o + (size_t)(hb + 0 * SPLIT) * 128 + lane * 4) = o0;
        *(float4*)(g_part_o + (size_t)(hb + 1 * SPLIT) * 128 + lane * 4) = o1;
        *(float4*)(g_part_o + (size_t)(hb + 2 * SPLIT) * 128 + lane * 4) = o2;
        *(float4*)(g_part_o + (size_t)(hb + 3 * SPLIT) * 128 + lane * 4) = o3;
        if (lane < 4) {
            int pidx = hb + lane * SPLIT;
            g_part_ml[pidx * 2]     = rm;
            g_part_ml[pidx * 2 + 1] = rl;
        }
    }
}

// ---------------- kernel 5: split-KV softmax combine -> attn out fragments (tf32 hi/lo) ----------------
__global__ void attn_combine_kernel() {
    const int qh = blockIdx.x & 31;
    const int b = blockIdx.x >> 5;
    const int kvh = qh >> 2, h = qh & 3;
    const int pidx = ((b * 8 + kvh) * 4 + h) * SPLIT;
    const int d = threadIdx.x;

    float M = -1e30f;
#pragma unroll
    for (int g = 0; g < SPLIT; g++)
        M = fmaxf(M, g_part_ml[(pidx + g) * 2]);

    float L = 0.f, s = 0.f;
#pragma unroll 4
    for (int g = 0; g < SPLIT; g++) {
        float w = ex2f_fast(g_part_ml[(pidx + g) * 2] - M);
        L += g_part_ml[(pidx + g) * 2 + 1] * w;
        s += g_part_o[(size_t)(pidx + g) * 128 + d] * w;
    }

    float v = s / L;
    float hif = __uint_as_float(tf32_rna(v));
    float lof = v - hif;
    int fi = frag_idx(qh * 128 + d, b);
    g_afh[fi] = hif;
    g_afl[fi] = __uint_as_float(tf32_rna(lof));
}

// ---------------- kernel 8: out combine — sum k-splits -> final output ----------------
__global__ void out_combine_kernel(float* __restrict__ outp) {
    const int idx = blockIdx.x * 256 + threadIdx.x;   // 65536 = 16 b x 4096 rows
    const int b = idx >> 12, r = idx & 4095;
    float s = 0.f;
#pragma unroll 8
    for (int ks = 0; ks < KSO; ks++)
        s += g_partO[((size_t)ks * 4096 + r) * 16 + b];
    outp[b * 4096 + r] = s;
}

// ---------------- launch ----------------
extern "C" void kernel_launch(void* const* d_in, const int* in_sizes, int n_in,
                              void* d_out, int out_size) {
    const float* x  = (const float*)d_in[0];
    const int*   sp = (const int*)d_in[1];
    const float* fc = (const float*)d_in[2];
    const float* fs = (const float*)d_in[3];
    const float* ck = (const float*)d_in[4];
    const float* cv = (const float*)d_in[5];
    const float* wq = (const float*)d_in[6];
    const float* wk = (const float*)d_in[7];
    const float* wv = (const float*)d_in[8];
    const float* wo = (const float*)d_in[9];
    float* out = (float*)d_out;

    dummy_kernel<<<1, 32>>>();
    dummy_kernel<<<1, 32>>>();
    prep_x_kernel<<<256, dim3(16, 16)>>>(x);
    gemv_mma_kernel<<<48 * KSQ, 128>>>(wq, wk, wv, 0);           // QKV projection (768 blocks)
    qkv_combine_kernel<<<192, 256>>>(fc, fs);
    attn_partial_kernel<<<16 * SPLIT, 256>>>(ck, cv, sp);
    attn_combine_kernel<<<512, 128>>>();
    gemv_mma_kernel<<<32 * KSO, 128>>>(wo, nullptr, nullptr, 1); // out projection (512 blocks)
    out_combine_kernel<<<256, 256>>>(out);
}